// round 14
// baseline (speedup 1.0000x reference)
#include <cuda_runtime.h>
#include <math.h>

// ---------------------------------------------------------------------------
// GCN 2-layer, CSR-gather with factored symmetric norm:
//   hs = (x@W) scaled by dinv[row] in GEMM epilogue
//   agg[c] = dinv[c] * ( hs[c] + sum_{e: col=c} hs[row_e] )   — plain sum
//   CSR stores ONLY row indices (4 B/edge).
// Prep chain = 4 launches: count -> scanA -> scanC(fused dinv+prefix+clean)
//   -> fill.  count/fill process 4 edges/thread via int4 loads (MLP=4).
//   g_cnt is zero at entry (module-load init + scanC self-clean).
// edge_index arrives as int32 (JAX x64 disabled downcasts int64).
// ---------------------------------------------------------------------------

#define NN 50000
#define EE 800000
#define F1 128
#define F2 64
#define F3 40
#define SCAN_BS 512
#define MAX_NB 128     // ceil(50000/512)=98 <= 128

// Scratch (device globals: no allocation allowed; zero-initialized at load)
__device__ int   g_cnt[NN];            // in-degree; ALWAYS zero at entry
__device__ float g_dinv[NN];           // 1/sqrt(deg+1)
__device__ int   g_off[NN + 1];        // CSR offsets
__device__ int   g_cur[NN];            // fill cursors
__device__ int   g_bsum[MAX_NB];       // scan partials
__device__ int   g_csri[EE];           // CSR row indices only
__device__ __align__(16) float g_h1[NN * F2];     // dinv-scaled x@W1
__device__ __align__(16) float g_agg1[NN * F2];   // layer-1 aggregation
__device__ __align__(16) float g_h2[NN * F3];     // dinv-scaled relu(agg1+b1)@W2

// ---------------------------------------------------------------------------
// count: 4 edges per thread via one int4 load of col indices (MLP=4)
__global__ void k_count(const int* __restrict__ ei, int E) {
    int q = blockIdx.x * blockDim.x + threadIdx.x;   // quad index
    int e4 = q * 4;
    if (e4 + 4 <= E) {
        int4 c = *(const int4*)(ei + E + e4);
        atomicAdd(&g_cnt[c.x], 1);
        atomicAdd(&g_cnt[c.y], 1);
        atomicAdd(&g_cnt[c.z], 1);
        atomicAdd(&g_cnt[c.w], 1);
    } else {
        for (int e = e4; e < E; e++) atomicAdd(&g_cnt[ei[E + e]], 1);
    }
}

// scan step A: per-block sums of g_cnt
__global__ void k_scanA(int N) {
    __shared__ int s[SCAN_BS];
    int i = blockIdx.x * SCAN_BS + threadIdx.x;
    s[threadIdx.x] = (i < N) ? g_cnt[i] : 0;
    __syncthreads();
    for (int st = SCAN_BS / 2; st > 0; st >>= 1) {
        if (threadIdx.x < st) s[threadIdx.x] += s[threadIdx.x + st];
        __syncthreads();
    }
    if (threadIdx.x == 0 && blockIdx.x < MAX_NB) g_bsum[blockIdx.x] = s[0];
}

// scan step C (fused): intra-block scan + own block-prefix from g_bsum +
// offsets + cursors + dinv + self-clean of g_cnt for the next replay.
__global__ void k_scanC(int N, int E) {
    __shared__ int s[SCAN_BS];
    __shared__ int bs_sh[MAX_NB];
    __shared__ int bpre_sh;
    const int t = threadIdx.x;
    const int i = blockIdx.x * SCAN_BS + t;

    int v = (i < N) ? g_cnt[i] : 0;
    if (i < N) g_cnt[i] = 0;              // self-clean for next graph replay
    s[t] = v;
    if (t < MAX_NB) bs_sh[t] = (t < blockIdx.x) ? g_bsum[t] : 0;
    __syncthreads();
#pragma unroll
    for (int st = 1; st < SCAN_BS; st <<= 1) {
        int add = (t >= st) ? s[t - st] : 0;
        __syncthreads();
        s[t] += add;
        __syncthreads();
    }
    if (t == 0) {
        int run = 0;
        for (int b = 0; b < MAX_NB; b++) run += bs_sh[b];
        bpre_sh = run;
    }
    __syncthreads();
    if (i < N) {
        int excl = bpre_sh + s[t] - v;    // exclusive prefix
        g_off[i] = excl;
        g_cur[i] = excl;
        g_dinv[i] = rsqrtf((float)v + 1.0f);
    }
    if (i == 0) g_off[N] = E;
}

// fill CSR: 4 edges per thread via int4 loads of rows and cols (MLP=4)
__global__ void k_fill(const int* __restrict__ ei, int E) {
    int q = blockIdx.x * blockDim.x + threadIdx.x;
    int e4 = q * 4;
    if (e4 + 4 <= E) {
        int4 r = *(const int4*)(ei + e4);
        int4 c = *(const int4*)(ei + E + e4);
        int p0 = atomicAdd(&g_cur[c.x], 1);
        int p1 = atomicAdd(&g_cur[c.y], 1);
        int p2 = atomicAdd(&g_cur[c.z], 1);
        int p3 = atomicAdd(&g_cur[c.w], 1);
        g_csri[p0] = r.x;
        g_csri[p1] = r.y;
        g_csri[p2] = r.z;
        g_csri[p3] = r.w;
    } else {
        for (int e = e4; e < E; e++) {
            int p = atomicAdd(&g_cur[ei[E + e]], 1);
            g_csri[p] = ei[e];
        }
    }
}

// ---------------------------------------------------------------------------
// GEMM1: h1s[N,64] = dinv[row] * (x[N,128] @ W1[128,64])
__global__ void k_gemm1(const float* __restrict__ x, const float* __restrict__ W,
                        int N) {
    __shared__ float Ws[32][64];
    __shared__ float Xs[32][68];
    const int bro = blockIdx.x * 64;
    const int t = threadIdx.x;
    const int tr = t >> 4;
    const int tc = t & 15;

    float acc[4][4];
#pragma unroll
    for (int i = 0; i < 4; i++)
#pragma unroll
        for (int j = 0; j < 4; j++) acc[i][j] = 0.0f;

    for (int k0 = 0; k0 < F1; k0 += 32) {
        {
            const float4* Wg = (const float4*)(W + k0 * 64);
            float4* Wsm = (float4*)&Ws[0][0];
            Wsm[t] = Wg[t];
            Wsm[t + 256] = Wg[t + 256];
        }
#pragma unroll
        for (int it = 0; it < 2; it++) {
            int idx = t + it * 256;
            int row = idx >> 3;
            int kq = idx & 7;
            int grow = bro + row;
            float4 v = make_float4(0.f, 0.f, 0.f, 0.f);
            if (grow < N)
                v = *(const float4*)(x + (size_t)grow * F1 + k0 + kq * 4);
            Xs[kq * 4 + 0][row] = v.x;
            Xs[kq * 4 + 1][row] = v.y;
            Xs[kq * 4 + 2][row] = v.z;
            Xs[kq * 4 + 3][row] = v.w;
        }
        __syncthreads();
#pragma unroll
        for (int k = 0; k < 32; k++) {
            float4 a = *(const float4*)&Xs[k][tr * 4];
            float4 b = *(const float4*)&Ws[k][tc * 4];
            float av[4] = {a.x, a.y, a.z, a.w};
            float bv[4] = {b.x, b.y, b.z, b.w};
#pragma unroll
            for (int i = 0; i < 4; i++)
#pragma unroll
                for (int j = 0; j < 4; j++) acc[i][j] = fmaf(av[i], bv[j], acc[i][j]);
        }
        __syncthreads();
    }
#pragma unroll
    for (int i = 0; i < 4; i++) {
        int row = bro + tr * 4 + i;
        if (row < N) {
            float dr = g_dinv[row];
            float4 v = make_float4(dr * acc[i][0], dr * acc[i][1],
                                   dr * acc[i][2], dr * acc[i][3]);
            *(float4*)&g_h1[(size_t)row * F2 + tc * 4] = v;
        }
    }
}

// ---------------------------------------------------------------------------
// gather layer 1: warp per node, lane owns 2 feature cols (64 = 32*2)
// plain sum of pre-scaled rows; final multiply by dinv[c]; x4 unroll for MLP
__global__ void k_gather1(int N) {
    int warp = (blockIdx.x * blockDim.x + threadIdx.x) >> 5;
    int lane = threadIdx.x & 31;
    if (warp >= N) return;
    const int c = warp;

    float2 self = *(const float2*)&g_h1[(size_t)c * F2 + lane * 2];
    float ax = self.x, ay = self.y;

    int j = g_off[c];
    const int end = g_off[c + 1];
    for (; j + 4 <= end; j += 4) {
        int r0 = __ldg(&g_csri[j + 0]);
        int r1 = __ldg(&g_csri[j + 1]);
        int r2 = __ldg(&g_csri[j + 2]);
        int r3 = __ldg(&g_csri[j + 3]);
        float2 v0 = *(const float2*)&g_h1[(size_t)r0 * F2 + lane * 2];
        float2 v1 = *(const float2*)&g_h1[(size_t)r1 * F2 + lane * 2];
        float2 v2 = *(const float2*)&g_h1[(size_t)r2 * F2 + lane * 2];
        float2 v3 = *(const float2*)&g_h1[(size_t)r3 * F2 + lane * 2];
        ax += v0.x + v1.x + v2.x + v3.x;
        ay += v0.y + v1.y + v2.y + v3.y;
    }
    for (; j < end; j++) {
        int r = __ldg(&g_csri[j]);
        float2 v = *(const float2*)&g_h1[(size_t)r * F2 + lane * 2];
        ax += v.x;
        ay += v.y;
    }
    float d = g_dinv[c];
    *(float2*)&g_agg1[(size_t)c * F2 + lane * 2] = make_float2(d * ax, d * ay);
}

// ---------------------------------------------------------------------------
// GEMM2: h2s[N,40] = dinv[row] * (relu(agg1 + b1)[N,64] @ W2[64,40])
__global__ void k_gemm2(const float* __restrict__ W2, const float* __restrict__ b1,
                        int N) {
    __shared__ float Ws[64][40];
    __shared__ float As[64][68];
    __shared__ float bs[64];
    const int bro = blockIdx.x * 64;
    const int t = threadIdx.x;

    for (int idx = t; idx < 64 * 40; idx += 256) ((float*)Ws)[idx] = W2[idx];
    if (t < 64) bs[t] = b1[t];
    __syncthreads();

#pragma unroll
    for (int it = 0; it < 4; it++) {
        int idx = t + it * 256;
        int row = idx >> 4;
        int kq = idx & 15;
        int grow = bro + row;
        float4 v = make_float4(0.f, 0.f, 0.f, 0.f);
        if (grow < N)
            v = *(const float4*)&g_agg1[(size_t)grow * F2 + kq * 4];
        As[kq * 4 + 0][row] = fmaxf(v.x + bs[kq * 4 + 0], 0.0f);
        As[kq * 4 + 1][row] = fmaxf(v.y + bs[kq * 4 + 1], 0.0f);
        As[kq * 4 + 2][row] = fmaxf(v.z + bs[kq * 4 + 2], 0.0f);
        As[kq * 4 + 3][row] = fmaxf(v.w + bs[kq * 4 + 3], 0.0f);
    }
    __syncthreads();

    const int tr = t >> 3;
    const int tc = t & 7;
    float acc[2][5];
#pragma unroll
    for (int i = 0; i < 2; i++)
#pragma unroll
        for (int j = 0; j < 5; j++) acc[i][j] = 0.0f;

#pragma unroll
    for (int k = 0; k < 64; k++) {
        float2 a = *(const float2*)&As[k][tr * 2];
        float w0 = Ws[k][tc * 5 + 0];
        float w1 = Ws[k][tc * 5 + 1];
        float w2 = Ws[k][tc * 5 + 2];
        float w3 = Ws[k][tc * 5 + 3];
        float w4 = Ws[k][tc * 5 + 4];
        acc[0][0] = fmaf(a.x, w0, acc[0][0]);
        acc[0][1] = fmaf(a.x, w1, acc[0][1]);
        acc[0][2] = fmaf(a.x, w2, acc[0][2]);
        acc[0][3] = fmaf(a.x, w3, acc[0][3]);
        acc[0][4] = fmaf(a.x, w4, acc[0][4]);
        acc[1][0] = fmaf(a.y, w0, acc[1][0]);
        acc[1][1] = fmaf(a.y, w1, acc[1][1]);
        acc[1][2] = fmaf(a.y, w2, acc[1][2]);
        acc[1][3] = fmaf(a.y, w3, acc[1][3]);
        acc[1][4] = fmaf(a.y, w4, acc[1][4]);
    }
#pragma unroll
    for (int i = 0; i < 2; i++) {
        int row = bro + tr * 2 + i;
        if (row < N) {
            float dr = g_dinv[row];
#pragma unroll
            for (int j = 0; j < 5; j++)
                g_h2[(size_t)row * F3 + tc * 5 + j] = dr * acc[i][j];
        }
    }
}

// ---------------------------------------------------------------------------
// gather layer 2 + final scale + bias + fused log_softmax epilogue
// warp per node; lanes 0..19 own 2 feature cols; all 32 lanes stay alive
// for the warp reductions (inactive lanes contribute -INF / 0).
__global__ void k_gather2(float* __restrict__ out, const float* __restrict__ b2,
                          int N) {
    int warp = (blockIdx.x * blockDim.x + threadIdx.x) >> 5;
    int lane = threadIdx.x & 31;
    if (warp >= N) return;
    const int c = warp;
    const bool act = (lane < 20);
    const int col = act ? lane : 0;       // clamped float2 column index
    const float2* __restrict__ H = (const float2*)g_h2;   // row = 20 float2

    float2 s = H[(size_t)c * 20 + col];
    float ax = s.x, ay = s.y;

    int j = g_off[c];
    const int end = g_off[c + 1];
    for (; j + 4 <= end; j += 4) {
        int r0 = __ldg(&g_csri[j + 0]);
        int r1 = __ldg(&g_csri[j + 1]);
        int r2 = __ldg(&g_csri[j + 2]);
        int r3 = __ldg(&g_csri[j + 3]);
        float2 v0 = H[(size_t)r0 * 20 + col];
        float2 v1 = H[(size_t)r1 * 20 + col];
        float2 v2 = H[(size_t)r2 * 20 + col];
        float2 v3 = H[(size_t)r3 * 20 + col];
        ax += v0.x + v1.x + v2.x + v3.x;
        ay += v0.y + v1.y + v2.y + v3.y;
    }
    for (; j < end; j++) {
        int r = __ldg(&g_csri[j]);
        float2 v = H[(size_t)r * 20 + col];
        ax += v.x;
        ay += v.y;
    }

    // final dinv[c] scale, + b2, then log_softmax across the 40 values
    float d = g_dinv[c];
    if (act) {
        float2 b = ((const float2*)b2)[lane];
        ax = d * ax + b.x;
        ay = d * ay + b.y;
    } else {
        ax = -INFINITY; ay = -INFINITY;
    }
    float m = fmaxf(ax, ay);
#pragma unroll
    for (int st = 16; st > 0; st >>= 1)
        m = fmaxf(m, __shfl_xor_sync(0xFFFFFFFFu, m, st));

    float es = act ? (expf(ax - m) + expf(ay - m)) : 0.0f;
#pragma unroll
    for (int st = 16; st > 0; st >>= 1)
        es += __shfl_xor_sync(0xFFFFFFFFu, es, st);

    float l = m + logf(es);
    if (act)
        ((float2*)out)[(size_t)c * 20 + lane] = make_float2(ax - l, ay - l);
}

// ---------------------------------------------------------------------------
extern "C" void kernel_launch(void* const* d_in, const int* in_sizes, int n_in,
                              void* d_out, int out_size) {
    const float* x   = (const float*)d_in[0];
    const int* ei    = (const int*)d_in[1];   // int32 (JAX x64 disabled)
    const float* W1  = (const float*)d_in[2];
    const float* b1  = (const float*)d_in[3];
    const float* W2  = (const float*)d_in[4];
    const float* b2  = (const float*)d_in[5];
    float* out       = (float*)d_out;

    const int N = in_sizes[0] / F1;
    const int E = in_sizes[1] / 2;
    const int NB = (N + SCAN_BS - 1) / SCAN_BS;
    const int EQ = (E + 3) / 4;               // edge quads

    // CSR build — 4 launches (g_cnt is zero at entry: load-init + self-clean)
    k_count<<<(EQ + 255) / 256, 256>>>(ei, E);
    k_scanA<<<NB, SCAN_BS>>>(N);
    k_scanC<<<NB, SCAN_BS>>>(N, E);
    k_fill<<<(EQ + 255) / 256, 256>>>(ei, E);

    // layer 1
    k_gemm1<<<(N + 63) / 64, 256>>>(x, W1, N);
    k_gather1<<<(N + 7) / 8, 256>>>(N);

    // layer 2 (+fused epilogue)
    k_gemm2<<<(N + 63) / 64, 256>>>(W2, b1, N);
    k_gather2<<<(N + 7) / 8, 256>>>(out, b2, N);
}

// round 16
// speedup vs baseline: 1.0940x; 1.0940x over previous
#include <cuda_runtime.h>
#include <math.h>

// ---------------------------------------------------------------------------
// GCN 2-layer, CSR-gather with factored symmetric norm:
//   hs = (x@W) scaled by dinv[row] in GEMM epilogue
//   agg[c] = dinv[c] * ( hs[c] + sum_{e: col=c} hs[row_e] )   — plain sum
//   CSR stores ONLY row indices (4 B/edge).
// Launch chain (7): count -> scanA -> scanC -> [fill ∥ gemm1 fat kernel]
//   -> gather1 -> gemm2 -> gather2(+log_softmax).
// fill & gemm1 are independent (both need only scanC) — fused into one fat
// kernel for single-stream concurrency under graph capture.
// g_cnt is zero at entry (module-load init + scanC self-clean).
// edge_index arrives as int32 (JAX x64 disabled downcasts int64).
// ---------------------------------------------------------------------------

#define NN 50000
#define EE 800000
#define F1 128
#define F2 64
#define F3 40
#define SCAN_BS 512
#define MAX_NB 128     // ceil(50000/512)=98 <= 128

// Scratch (device globals: no allocation allowed; zero-initialized at load)
__device__ int   g_cnt[NN];            // in-degree; ALWAYS zero at entry
__device__ float g_dinv[NN];           // 1/sqrt(deg+1)
__device__ int   g_off[NN + 1];        // CSR offsets
__device__ int   g_cur[NN];            // fill cursors
__device__ int   g_bsum[MAX_NB];       // scan partials
__device__ int   g_csri[EE];           // CSR row indices only
__device__ __align__(16) float g_h1[NN * F2];     // dinv-scaled x@W1
__device__ __align__(16) float g_agg1[NN * F2];   // layer-1 aggregation
__device__ __align__(16) float g_h2[NN * F3];     // dinv-scaled relu(agg1+b1)@W2

// ---------------------------------------------------------------------------
__global__ void k_count(const int* __restrict__ ei, int E) {
    int e = blockIdx.x * blockDim.x + threadIdx.x;
    if (e < E) atomicAdd(&g_cnt[ei[E + e]], 1);
}

// scan step A: per-block sums of g_cnt
__global__ void k_scanA(int N) {
    __shared__ int s[SCAN_BS];
    int i = blockIdx.x * SCAN_BS + threadIdx.x;
    s[threadIdx.x] = (i < N) ? g_cnt[i] : 0;
    __syncthreads();
    for (int st = SCAN_BS / 2; st > 0; st >>= 1) {
        if (threadIdx.x < st) s[threadIdx.x] += s[threadIdx.x + st];
        __syncthreads();
    }
    if (threadIdx.x == 0 && blockIdx.x < MAX_NB) g_bsum[blockIdx.x] = s[0];
}

// scan step C (fused): intra-block scan + own block-prefix from g_bsum +
// offsets + cursors + dinv + self-clean of g_cnt for the next replay.
__global__ void k_scanC(int N, int E) {
    __shared__ int s[SCAN_BS];
    __shared__ int bs_sh[MAX_NB];
    __shared__ int bpre_sh;
    const int t = threadIdx.x;
    const int i = blockIdx.x * SCAN_BS + t;

    int v = (i < N) ? g_cnt[i] : 0;
    if (i < N) g_cnt[i] = 0;              // self-clean for next graph replay
    s[t] = v;
    if (t < MAX_NB) bs_sh[t] = (t < blockIdx.x) ? g_bsum[t] : 0;
    __syncthreads();
#pragma unroll
    for (int st = 1; st < SCAN_BS; st <<= 1) {
        int add = (t >= st) ? s[t - st] : 0;
        __syncthreads();
        s[t] += add;
        __syncthreads();
    }
    if (t == 0) {
        int run = 0;
        for (int b = 0; b < MAX_NB; b++) run += bs_sh[b];
        bpre_sh = run;
    }
    __syncthreads();
    if (i < N) {
        int excl = bpre_sh + s[t] - v;    // exclusive prefix
        g_off[i] = excl;
        g_cur[i] = excl;
        g_dinv[i] = rsqrtf((float)v + 1.0f);
    }
    if (i == 0) g_off[N] = E;
}

// ---------------------------------------------------------------------------
// FAT KERNEL: blocks [0, gemmBlocks) run GEMM1; the rest run CSR fill.
// Both depend only on scanC; fusing them overlaps the latency-bound fill
// with the compute-bound GEMM on a single capture-safe stream.
// GEMM1: h1s[N,64] = dinv[row] * (x[N,128] @ W1[128,64])
// fill:  g_csri[cursor(col)++] = row  (scalar, 1 edge/thread: warp-count
//        latency hiding — int4/MLP variant measured SLOWER in R14)
__global__ void k_fill_gemm1(const float* __restrict__ x,
                             const float* __restrict__ W,
                             const int* __restrict__ ei,
                             int N, int E, int gemmBlocks) {
    __shared__ float Ws[32][64];
    __shared__ float Xs[32][68];

    if (blockIdx.x >= gemmBlocks) {
        // ---- fill branch (block-granular; skips all __syncthreads) ----
        int e = (blockIdx.x - gemmBlocks) * blockDim.x + threadIdx.x;
        if (e < E) {
            int r = ei[e];
            int c = ei[E + e];
            int p = atomicAdd(&g_cur[c], 1);
            g_csri[p] = r;
        }
        return;
    }

    // ---- GEMM1 branch ----
    const int bro = blockIdx.x * 64;
    const int t = threadIdx.x;
    const int tr = t >> 4;
    const int tc = t & 15;

    float acc[4][4];
#pragma unroll
    for (int i = 0; i < 4; i++)
#pragma unroll
        for (int j = 0; j < 4; j++) acc[i][j] = 0.0f;

    for (int k0 = 0; k0 < F1; k0 += 32) {
        {
            const float4* Wg = (const float4*)(W + k0 * 64);
            float4* Wsm = (float4*)&Ws[0][0];
            Wsm[t] = Wg[t];
            Wsm[t + 256] = Wg[t + 256];
        }
#pragma unroll
        for (int it = 0; it < 2; it++) {
            int idx = t + it * 256;
            int row = idx >> 3;
            int kq = idx & 7;
            int grow = bro + row;
            float4 v = make_float4(0.f, 0.f, 0.f, 0.f);
            if (grow < N)
                v = *(const float4*)(x + (size_t)grow * F1 + k0 + kq * 4);
            Xs[kq * 4 + 0][row] = v.x;
            Xs[kq * 4 + 1][row] = v.y;
            Xs[kq * 4 + 2][row] = v.z;
            Xs[kq * 4 + 3][row] = v.w;
        }
        __syncthreads();
#pragma unroll
        for (int k = 0; k < 32; k++) {
            float4 a = *(const float4*)&Xs[k][tr * 4];
            float4 b = *(const float4*)&Ws[k][tc * 4];
            float av[4] = {a.x, a.y, a.z, a.w};
            float bv[4] = {b.x, b.y, b.z, b.w};
#pragma unroll
            for (int i = 0; i < 4; i++)
#pragma unroll
                for (int j = 0; j < 4; j++) acc[i][j] = fmaf(av[i], bv[j], acc[i][j]);
        }
        __syncthreads();
    }
#pragma unroll
    for (int i = 0; i < 4; i++) {
        int row = bro + tr * 4 + i;
        if (row < N) {
            float dr = g_dinv[row];
            float4 v = make_float4(dr * acc[i][0], dr * acc[i][1],
                                   dr * acc[i][2], dr * acc[i][3]);
            *(float4*)&g_h1[(size_t)row * F2 + tc * 4] = v;
        }
    }
}

// ---------------------------------------------------------------------------
// gather layer 1: warp per node, lane owns 2 feature cols (64 = 32*2)
// plain sum of pre-scaled rows; final multiply by dinv[c]; x4 unroll for MLP
__global__ void k_gather1(int N) {
    int warp = (blockIdx.x * blockDim.x + threadIdx.x) >> 5;
    int lane = threadIdx.x & 31;
    if (warp >= N) return;
    const int c = warp;

    float2 self = *(const float2*)&g_h1[(size_t)c * F2 + lane * 2];
    float ax = self.x, ay = self.y;

    int j = g_off[c];
    const int end = g_off[c + 1];
    for (; j + 4 <= end; j += 4) {
        int r0 = __ldg(&g_csri[j + 0]);
        int r1 = __ldg(&g_csri[j + 1]);
        int r2 = __ldg(&g_csri[j + 2]);
        int r3 = __ldg(&g_csri[j + 3]);
        float2 v0 = *(const float2*)&g_h1[(size_t)r0 * F2 + lane * 2];
        float2 v1 = *(const float2*)&g_h1[(size_t)r1 * F2 + lane * 2];
        float2 v2 = *(const float2*)&g_h1[(size_t)r2 * F2 + lane * 2];
        float2 v3 = *(const float2*)&g_h1[(size_t)r3 * F2 + lane * 2];
        ax += v0.x + v1.x + v2.x + v3.x;
        ay += v0.y + v1.y + v2.y + v3.y;
    }
    for (; j < end; j++) {
        int r = __ldg(&g_csri[j]);
        float2 v = *(const float2*)&g_h1[(size_t)r * F2 + lane * 2];
        ax += v.x;
        ay += v.y;
    }
    float d = g_dinv[c];
    *(float2*)&g_agg1[(size_t)c * F2 + lane * 2] = make_float2(d * ax, d * ay);
}

// ---------------------------------------------------------------------------
// GEMM2: h2s[N,40] = dinv[row] * (relu(agg1 + b1)[N,64] @ W2[64,40])
__global__ void k_gemm2(const float* __restrict__ W2, const float* __restrict__ b1,
                        int N) {
    __shared__ float Ws[64][40];
    __shared__ float As[64][68];
    __shared__ float bs[64];
    const int bro = blockIdx.x * 64;
    const int t = threadIdx.x;

    for (int idx = t; idx < 64 * 40; idx += 256) ((float*)Ws)[idx] = W2[idx];
    if (t < 64) bs[t] = b1[t];
    __syncthreads();

#pragma unroll
    for (int it = 0; it < 4; it++) {
        int idx = t + it * 256;
        int row = idx >> 4;
        int kq = idx & 15;
        int grow = bro + row;
        float4 v = make_float4(0.f, 0.f, 0.f, 0.f);
        if (grow < N)
            v = *(const float4*)&g_agg1[(size_t)grow * F2 + kq * 4];
        As[kq * 4 + 0][row] = fmaxf(v.x + bs[kq * 4 + 0], 0.0f);
        As[kq * 4 + 1][row] = fmaxf(v.y + bs[kq * 4 + 1], 0.0f);
        As[kq * 4 + 2][row] = fmaxf(v.z + bs[kq * 4 + 2], 0.0f);
        As[kq * 4 + 3][row] = fmaxf(v.w + bs[kq * 4 + 3], 0.0f);
    }
    __syncthreads();

    const int tr = t >> 3;
    const int tc = t & 7;
    float acc[2][5];
#pragma unroll
    for (int i = 0; i < 2; i++)
#pragma unroll
        for (int j = 0; j < 5; j++) acc[i][j] = 0.0f;

#pragma unroll
    for (int k = 0; k < 64; k++) {
        float2 a = *(const float2*)&As[k][tr * 2];
        float w0 = Ws[k][tc * 5 + 0];
        float w1 = Ws[k][tc * 5 + 1];
        float w2 = Ws[k][tc * 5 + 2];
        float w3 = Ws[k][tc * 5 + 3];
        float w4 = Ws[k][tc * 5 + 4];
        acc[0][0] = fmaf(a.x, w0, acc[0][0]);
        acc[0][1] = fmaf(a.x, w1, acc[0][1]);
        acc[0][2] = fmaf(a.x, w2, acc[0][2]);
        acc[0][3] = fmaf(a.x, w3, acc[0][3]);
        acc[0][4] = fmaf(a.x, w4, acc[0][4]);
        acc[1][0] = fmaf(a.y, w0, acc[1][0]);
        acc[1][1] = fmaf(a.y, w1, acc[1][1]);
        acc[1][2] = fmaf(a.y, w2, acc[1][2]);
        acc[1][3] = fmaf(a.y, w3, acc[1][3]);
        acc[1][4] = fmaf(a.y, w4, acc[1][4]);
    }
#pragma unroll
    for (int i = 0; i < 2; i++) {
        int row = bro + tr * 2 + i;
        if (row < N) {
            float dr = g_dinv[row];
#pragma unroll
            for (int j = 0; j < 5; j++)
                g_h2[(size_t)row * F3 + tc * 5 + j] = dr * acc[i][j];
        }
    }
}

// ---------------------------------------------------------------------------
// gather layer 2 + final scale + bias + fused log_softmax epilogue
// warp per node; lanes 0..19 own 2 feature cols; all 32 lanes stay alive
// for the warp reductions (inactive lanes contribute -INF / 0).
__global__ void k_gather2(float* __restrict__ out, const float* __restrict__ b2,
                          int N) {
    int warp = (blockIdx.x * blockDim.x + threadIdx.x) >> 5;
    int lane = threadIdx.x & 31;
    if (warp >= N) return;
    const int c = warp;
    const bool act = (lane < 20);
    const int col = act ? lane : 0;       // clamped float2 column index
    const float2* __restrict__ H = (const float2*)g_h2;   // row = 20 float2

    float2 s = H[(size_t)c * 20 + col];
    float ax = s.x, ay = s.y;

    int j = g_off[c];
    const int end = g_off[c + 1];
    for (; j + 4 <= end; j += 4) {
        int r0 = __ldg(&g_csri[j + 0]);
        int r1 = __ldg(&g_csri[j + 1]);
        int r2 = __ldg(&g_csri[j + 2]);
        int r3 = __ldg(&g_csri[j + 3]);
        float2 v0 = H[(size_t)r0 * 20 + col];
        float2 v1 = H[(size_t)r1 * 20 + col];
        float2 v2 = H[(size_t)r2 * 20 + col];
        float2 v3 = H[(size_t)r3 * 20 + col];
        ax += v0.x + v1.x + v2.x + v3.x;
        ay += v0.y + v1.y + v2.y + v3.y;
    }
    for (; j < end; j++) {
        int r = __ldg(&g_csri[j]);
        float2 v = H[(size_t)r * 20 + col];
        ax += v.x;
        ay += v.y;
    }

    // final dinv[c] scale, + b2, then log_softmax across the 40 values
    float d = g_dinv[c];
    if (act) {
        float2 b = ((const float2*)b2)[lane];
        ax = d * ax + b.x;
        ay = d * ay + b.y;
    } else {
        ax = -INFINITY; ay = -INFINITY;
    }
    float m = fmaxf(ax, ay);
#pragma unroll
    for (int st = 16; st > 0; st >>= 1)
        m = fmaxf(m, __shfl_xor_sync(0xFFFFFFFFu, m, st));

    float es = act ? (expf(ax - m) + expf(ay - m)) : 0.0f;
#pragma unroll
    for (int st = 16; st > 0; st >>= 1)
        es += __shfl_xor_sync(0xFFFFFFFFu, es, st);

    float l = m + logf(es);
    if (act)
        ((float2*)out)[(size_t)c * 20 + lane] = make_float2(ax - l, ay - l);
}

// ---------------------------------------------------------------------------
extern "C" void kernel_launch(void* const* d_in, const int* in_sizes, int n_in,
                              void* d_out, int out_size) {
    const float* x   = (const float*)d_in[0];
    const int* ei    = (const int*)d_in[1];   // int32 (JAX x64 disabled)
    const float* W1  = (const float*)d_in[2];
    const float* b1  = (const float*)d_in[3];
    const float* W2  = (const float*)d_in[4];
    const float* b2  = (const float*)d_in[5];
    float* out       = (float*)d_out;

    const int N = in_sizes[0] / F1;
    const int E = in_sizes[1] / 2;
    const int NB = (N + SCAN_BS - 1) / SCAN_BS;
    const int gemmBlocks = (N + 63) / 64;
    const int fillBlocks = (E + 255) / 256;

    // CSR prep
    k_count<<<(E + 255) / 256, 256>>>(ei, E);
    k_scanA<<<NB, SCAN_BS>>>(N);
    k_scanC<<<NB, SCAN_BS>>>(N, E);

    // fill ∥ gemm1 (fat kernel — both depend only on scanC)
    k_fill_gemm1<<<gemmBlocks + fillBlocks, 256>>>(x, W1, ei, N, E, gemmBlocks);

    // layer 1 aggregation
    k_gather1<<<(N + 7) / 8, 256>>>(N);

    // layer 2 (+fused epilogue)
    k_gemm2<<<(N + 63) / 64, 256>>>(W2, b1, N);
    k_gather2<<<(N + 7) / 8, 256>>>(out, b2, N);
}

// round 17
// speedup vs baseline: 1.1314x; 1.0342x over previous
#include <cuda_runtime.h>
#include <math.h>

// ---------------------------------------------------------------------------
// GCN 2-layer, CSR-gather with factored symmetric norm:
//   hs = (x@W) scaled by dinv[row] in GEMM epilogue
//   agg[c] = dinv[c] * ( hs[c] + sum_{e: col=c} hs[row_e] )   — plain sum
//   CSR stores ONLY row indices (4 B/edge).
// Launch chain (7): count -> scanA -> scanC -> [fill ∥ gemm1 fat kernel]
//   -> gather1 -> gemm2 -> gather2(+log_softmax).
// GEMM1 branch: 128x64 block tile, 8x4 thread tile (1.5 B LDS per FMA —
//   R16 profile showed L1 71.5% vs fma 31.5% on the old 64x64/4x4 tile).
// g_cnt is zero at entry (module-load init + scanC self-clean).
// edge_index arrives as int32 (JAX x64 disabled downcasts int64).
// ---------------------------------------------------------------------------

#define NN 50000
#define EE 800000
#define F1 128
#define F2 64
#define F3 40
#define SCAN_BS 512
#define MAX_NB 128     // ceil(50000/512)=98 <= 128

// Scratch (device globals: no allocation allowed; zero-initialized at load)
__device__ int   g_cnt[NN];            // in-degree; ALWAYS zero at entry
__device__ float g_dinv[NN];           // 1/sqrt(deg+1)
__device__ int   g_off[NN + 1];        // CSR offsets
__device__ int   g_cur[NN];            // fill cursors
__device__ int   g_bsum[MAX_NB];       // scan partials
__device__ int   g_csri[EE];           // CSR row indices only
__device__ __align__(16) float g_h1[NN * F2];     // dinv-scaled x@W1
__device__ __align__(16) float g_agg1[NN * F2];   // layer-1 aggregation
__device__ __align__(16) float g_h2[NN * F3];     // dinv-scaled relu(agg1+b1)@W2

// ---------------------------------------------------------------------------
__global__ void k_count(const int* __restrict__ ei, int E) {
    int e = blockIdx.x * blockDim.x + threadIdx.x;
    if (e < E) atomicAdd(&g_cnt[ei[E + e]], 1);
}

// scan step A: per-block sums of g_cnt
__global__ void k_scanA(int N) {
    __shared__ int s[SCAN_BS];
    int i = blockIdx.x * SCAN_BS + threadIdx.x;
    s[threadIdx.x] = (i < N) ? g_cnt[i] : 0;
    __syncthreads();
    for (int st = SCAN_BS / 2; st > 0; st >>= 1) {
        if (threadIdx.x < st) s[threadIdx.x] += s[threadIdx.x + st];
        __syncthreads();
    }
    if (threadIdx.x == 0 && blockIdx.x < MAX_NB) g_bsum[blockIdx.x] = s[0];
}

// scan step C (fused): intra-block scan + own block-prefix from g_bsum +
// offsets + cursors + dinv + self-clean of g_cnt for the next replay.
__global__ void k_scanC(int N, int E) {
    __shared__ int s[SCAN_BS];
    __shared__ int bs_sh[MAX_NB];
    __shared__ int bpre_sh;
    const int t = threadIdx.x;
    const int i = blockIdx.x * SCAN_BS + t;

    int v = (i < N) ? g_cnt[i] : 0;
    if (i < N) g_cnt[i] = 0;              // self-clean for next graph replay
    s[t] = v;
    if (t < MAX_NB) bs_sh[t] = (t < blockIdx.x) ? g_bsum[t] : 0;
    __syncthreads();
#pragma unroll
    for (int st = 1; st < SCAN_BS; st <<= 1) {
        int add = (t >= st) ? s[t - st] : 0;
        __syncthreads();
        s[t] += add;
        __syncthreads();
    }
    if (t == 0) {
        int run = 0;
        for (int b = 0; b < MAX_NB; b++) run += bs_sh[b];
        bpre_sh = run;
    }
    __syncthreads();
    if (i < N) {
        int excl = bpre_sh + s[t] - v;    // exclusive prefix
        g_off[i] = excl;
        g_cur[i] = excl;
        g_dinv[i] = rsqrtf((float)v + 1.0f);
    }
    if (i == 0) g_off[N] = E;
}

// ---------------------------------------------------------------------------
// FAT KERNEL: blocks [0, gemmBlocks) run GEMM1; the rest run CSR fill.
// GEMM1: h1s[N,64] = dinv[row] * (x[N,128] @ W1[128,64])
//   128x64 block tile, 8x4 per thread (16x16 thread grid), K chunk 32.
// fill:  g_csri[cursor(col)++] = row  (scalar; warp-count latency hiding)
__global__ void k_fill_gemm1(const float* __restrict__ x,
                             const float* __restrict__ W,
                             const int* __restrict__ ei,
                             int N, int E, int gemmBlocks) {
    __shared__ float Ws[32][64];     // 8 KB
    __shared__ float Xs[32][132];    // 16.9 KB, padded

    if (blockIdx.x >= gemmBlocks) {
        // ---- fill branch (block-granular; skips all __syncthreads) ----
        int e = (blockIdx.x - gemmBlocks) * blockDim.x + threadIdx.x;
        if (e < E) {
            int r = ei[e];
            int c = ei[E + e];
            int p = atomicAdd(&g_cur[c], 1);
            g_csri[p] = r;
        }
        return;
    }

    // ---- GEMM1 branch ----
    const int bro = blockIdx.x * 128;
    const int t = threadIdx.x;
    const int tr = t >> 4;           // 0..15 -> rows tr*8 .. tr*8+7
    const int tc = t & 15;           // 0..15 -> cols tc*4 .. tc*4+3

    float acc[8][4];
#pragma unroll
    for (int i = 0; i < 8; i++)
#pragma unroll
        for (int j = 0; j < 4; j++) acc[i][j] = 0.0f;

    for (int k0 = 0; k0 < F1; k0 += 32) {
        // load W chunk [32][64] = 512 float4, 2 per thread
        {
            const float4* Wg = (const float4*)(W + k0 * 64);
            float4* Wsm = (float4*)&Ws[0][0];
            Wsm[t] = Wg[t];
            Wsm[t + 256] = Wg[t + 256];
        }
        // load X chunk transposed: 128 rows x 32 k = 1024 float4, 4/thread
#pragma unroll
        for (int it = 0; it < 4; it++) {
            int idx = t + it * 256;
            int row = idx >> 3;       // 0..127
            int kq = idx & 7;         // float4 chunk within 32 k
            int grow = bro + row;
            float4 v = make_float4(0.f, 0.f, 0.f, 0.f);
            if (grow < N)
                v = *(const float4*)(x + (size_t)grow * F1 + k0 + kq * 4);
            Xs[kq * 4 + 0][row] = v.x;
            Xs[kq * 4 + 1][row] = v.y;
            Xs[kq * 4 + 2][row] = v.z;
            Xs[kq * 4 + 3][row] = v.w;
        }
        __syncthreads();
#pragma unroll
        for (int k = 0; k < 32; k++) {
            float4 a0 = *(const float4*)&Xs[k][tr * 8 + 0];
            float4 a1 = *(const float4*)&Xs[k][tr * 8 + 4];
            float4 b  = *(const float4*)&Ws[k][tc * 4];
            float av[8] = {a0.x, a0.y, a0.z, a0.w, a1.x, a1.y, a1.z, a1.w};
            float bv[4] = {b.x, b.y, b.z, b.w};
#pragma unroll
            for (int i = 0; i < 8; i++)
#pragma unroll
                for (int j = 0; j < 4; j++) acc[i][j] = fmaf(av[i], bv[j], acc[i][j]);
        }
        __syncthreads();
    }
#pragma unroll
    for (int i = 0; i < 8; i++) {
        int row = bro + tr * 8 + i;
        if (row < N) {
            float dr = g_dinv[row];
            float4 v = make_float4(dr * acc[i][0], dr * acc[i][1],
                                   dr * acc[i][2], dr * acc[i][3]);
            *(float4*)&g_h1[(size_t)row * F2 + tc * 4] = v;
        }
    }
}

// ---------------------------------------------------------------------------
// gather layer 1: warp per node, lane owns 2 feature cols (64 = 32*2)
// plain sum of pre-scaled rows; final multiply by dinv[c]; x4 unroll for MLP
__global__ void k_gather1(int N) {
    int warp = (blockIdx.x * blockDim.x + threadIdx.x) >> 5;
    int lane = threadIdx.x & 31;
    if (warp >= N) return;
    const int c = warp;

    float2 self = *(const float2*)&g_h1[(size_t)c * F2 + lane * 2];
    float ax = self.x, ay = self.y;

    int j = g_off[c];
    const int end = g_off[c + 1];
    for (; j + 4 <= end; j += 4) {
        int r0 = __ldg(&g_csri[j + 0]);
        int r1 = __ldg(&g_csri[j + 1]);
        int r2 = __ldg(&g_csri[j + 2]);
        int r3 = __ldg(&g_csri[j + 3]);
        float2 v0 = *(const float2*)&g_h1[(size_t)r0 * F2 + lane * 2];
        float2 v1 = *(const float2*)&g_h1[(size_t)r1 * F2 + lane * 2];
        float2 v2 = *(const float2*)&g_h1[(size_t)r2 * F2 + lane * 2];
        float2 v3 = *(const float2*)&g_h1[(size_t)r3 * F2 + lane * 2];
        ax += v0.x + v1.x + v2.x + v3.x;
        ay += v0.y + v1.y + v2.y + v3.y;
    }
    for (; j < end; j++) {
        int r = __ldg(&g_csri[j]);
        float2 v = *(const float2*)&g_h1[(size_t)r * F2 + lane * 2];
        ax += v.x;
        ay += v.y;
    }
    float d = g_dinv[c];
    *(float2*)&g_agg1[(size_t)c * F2 + lane * 2] = make_float2(d * ax, d * ay);
}

// ---------------------------------------------------------------------------
// GEMM2: h2s[N,40] = dinv[row] * (relu(agg1 + b1)[N,64] @ W2[64,40])
__global__ void k_gemm2(const float* __restrict__ W2, const float* __restrict__ b1,
                        int N) {
    __shared__ float Ws[64][40];
    __shared__ float As[64][68];
    __shared__ float bs[64];
    const int bro = blockIdx.x * 64;
    const int t = threadIdx.x;

    for (int idx = t; idx < 64 * 40; idx += 256) ((float*)Ws)[idx] = W2[idx];
    if (t < 64) bs[t] = b1[t];
    __syncthreads();

#pragma unroll
    for (int it = 0; it < 4; it++) {
        int idx = t + it * 256;
        int row = idx >> 4;
        int kq = idx & 15;
        int grow = bro + row;
        float4 v = make_float4(0.f, 0.f, 0.f, 0.f);
        if (grow < N)
            v = *(const float4*)&g_agg1[(size_t)grow * F2 + kq * 4];
        As[kq * 4 + 0][row] = fmaxf(v.x + bs[kq * 4 + 0], 0.0f);
        As[kq * 4 + 1][row] = fmaxf(v.y + bs[kq * 4 + 1], 0.0f);
        As[kq * 4 + 2][row] = fmaxf(v.z + bs[kq * 4 + 2], 0.0f);
        As[kq * 4 + 3][row] = fmaxf(v.w + bs[kq * 4 + 3], 0.0f);
    }
    __syncthreads();

    const int tr = t >> 3;
    const int tc = t & 7;
    float acc[2][5];
#pragma unroll
    for (int i = 0; i < 2; i++)
#pragma unroll
        for (int j = 0; j < 5; j++) acc[i][j] = 0.0f;

#pragma unroll
    for (int k = 0; k < 64; k++) {
        float2 a = *(const float2*)&As[k][tr * 2];
        float w0 = Ws[k][tc * 5 + 0];
        float w1 = Ws[k][tc * 5 + 1];
        float w2 = Ws[k][tc * 5 + 2];
        float w3 = Ws[k][tc * 5 + 3];
        float w4 = Ws[k][tc * 5 + 4];
        acc[0][0] = fmaf(a.x, w0, acc[0][0]);
        acc[0][1] = fmaf(a.x, w1, acc[0][1]);
        acc[0][2] = fmaf(a.x, w2, acc[0][2]);
        acc[0][3] = fmaf(a.x, w3, acc[0][3]);
        acc[0][4] = fmaf(a.x, w4, acc[0][4]);
        acc[1][0] = fmaf(a.y, w0, acc[1][0]);
        acc[1][1] = fmaf(a.y, w1, acc[1][1]);
        acc[1][2] = fmaf(a.y, w2, acc[1][2]);
        acc[1][3] = fmaf(a.y, w3, acc[1][3]);
        acc[1][4] = fmaf(a.y, w4, acc[1][4]);
    }
#pragma unroll
    for (int i = 0; i < 2; i++) {
        int row = bro + tr * 2 + i;
        if (row < N) {
            float dr = g_dinv[row];
#pragma unroll
            for (int j = 0; j < 5; j++)
                g_h2[(size_t)row * F3 + tc * 5 + j] = dr * acc[i][j];
        }
    }
}

// ---------------------------------------------------------------------------
// gather layer 2 + final scale + bias + fused log_softmax epilogue
// warp per node; lanes 0..19 own 2 feature cols; all 32 lanes stay alive
// for the warp reductions (inactive lanes contribute -INF / 0).
__global__ void k_gather2(float* __restrict__ out, const float* __restrict__ b2,
                          int N) {
    int warp = (blockIdx.x * blockDim.x + threadIdx.x) >> 5;
    int lane = threadIdx.x & 31;
    if (warp >= N) return;
    const int c = warp;
    const bool act = (lane < 20);
    const int col = act ? lane : 0;       // clamped float2 column index
    const float2* __restrict__ H = (const float2*)g_h2;   // row = 20 float2

    float2 s = H[(size_t)c * 20 + col];
    float ax = s.x, ay = s.y;

    int j = g_off[c];
    const int end = g_off[c + 1];
    for (; j + 4 <= end; j += 4) {
        int r0 = __ldg(&g_csri[j + 0]);
        int r1 = __ldg(&g_csri[j + 1]);
        int r2 = __ldg(&g_csri[j + 2]);
        int r3 = __ldg(&g_csri[j + 3]);
        float2 v0 = H[(size_t)r0 * 20 + col];
        float2 v1 = H[(size_t)r1 * 20 + col];
        float2 v2 = H[(size_t)r2 * 20 + col];
        float2 v3 = H[(size_t)r3 * 20 + col];
        ax += v0.x + v1.x + v2.x + v3.x;
        ay += v0.y + v1.y + v2.y + v3.y;
    }
    for (; j < end; j++) {
        int r = __ldg(&g_csri[j]);
        float2 v = H[(size_t)r * 20 + col];
        ax += v.x;
        ay += v.y;
    }

    // final dinv[c] scale, + b2, then log_softmax across the 40 values
    float d = g_dinv[c];
    if (act) {
        float2 b = ((const float2*)b2)[lane];
        ax = d * ax + b.x;
        ay = d * ay + b.y;
    } else {
        ax = -INFINITY; ay = -INFINITY;
    }
    float m = fmaxf(ax, ay);
#pragma unroll
    for (int st = 16; st > 0; st >>= 1)
        m = fmaxf(m, __shfl_xor_sync(0xFFFFFFFFu, m, st));

    float es = act ? (expf(ax - m) + expf(ay - m)) : 0.0f;
#pragma unroll
    for (int st = 16; st > 0; st >>= 1)
        es += __shfl_xor_sync(0xFFFFFFFFu, es, st);

    float l = m + logf(es);
    if (act)
        ((float2*)out)[(size_t)c * 20 + lane] = make_float2(ax - l, ay - l);
}

// ---------------------------------------------------------------------------
extern "C" void kernel_launch(void* const* d_in, const int* in_sizes, int n_in,
                              void* d_out, int out_size) {
    const float* x   = (const float*)d_in[0];
    const int* ei    = (const int*)d_in[1];   // int32 (JAX x64 disabled)
    const float* W1  = (const float*)d_in[2];
    const float* b1  = (const float*)d_in[3];
    const float* W2  = (const float*)d_in[4];
    const float* b2  = (const float*)d_in[5];
    float* out       = (float*)d_out;

    const int N = in_sizes[0] / F1;
    const int E = in_sizes[1] / 2;
    const int NB = (N + SCAN_BS - 1) / SCAN_BS;
    const int gemmBlocks = (N + 127) / 128;
    const int fillBlocks = (E + 255) / 256;

    // CSR prep
    k_count<<<(E + 255) / 256, 256>>>(ei, E);
    k_scanA<<<NB, SCAN_BS>>>(N);
    k_scanC<<<NB, SCAN_BS>>>(N, E);

    // fill ∥ gemm1 (fat kernel — both depend only on scanC)
    k_fill_gemm1<<<gemmBlocks + fillBlocks, 256>>>(x, W1, ei, N, E, gemmBlocks);

    // layer 1 aggregation
    k_gather1<<<(N + 7) / 8, 256>>>(N);

    // layer 2 (+fused epilogue)
    k_gemm2<<<(N + 63) / 64, 256>>>(W2, b1, N);
    k_gather2<<<(N + 7) / 8, 256>>>(out, b2, N);
}